// round 11
// baseline (speedup 1.0000x reference)
#include <cuda_runtime.h>
#include <cuda_fp16.h>
#include <math.h>
#include <stdint.h>

#define N_NODES 100000
#define E_EDGES 1000000
#define IN_DIM  128
#define OUT_DIM 64
#define H_HEADS 2
#define HO      (H_HEADS * OUT_DIM)   // 128

#define BLK_M   128
#define ZBLK    ((N_NODES + BLK_M - 1) / BLK_M)   // 782
#define SDBLK   (N_NODES / 16)                    // 6250
#define CAP     64     // max degree slots per dst (Poisson(10): P(deg>=64) ~ 1e-40)
#define PADH    136    // X tile row pad (halves)

// ---- scratch (device globals: allocation-free rule) ----
__device__ __half  Z_H[(size_t)N_NODES * HO];       // z_src fp16, 25.6 MB (L2-resident)
__device__ float   S_SRC[N_NODES * H_HEADS];
__device__ float   S_DST[N_NODES * H_HEADS];
__device__ float   W_EFF_SRC[H_HEADS * IN_DIM];
__device__ float   W_EFF_DST[H_HEADS * IN_DIM];
__device__ uint2   W_FRH[HO * IN_DIM / 4];          // W_src fp16, frag-major
__device__ uint2   ENT[(size_t)N_NODES * CAP];      // (half2(ex0,ex1), src) 51.2 MB
__device__ int     COUNT[N_NODES];

// fp16 m16n8k16 MMA, fp32 accumulate (sm_80+ PTX -> Blackwell tensor pipe)
__device__ __forceinline__ void mma_f16(float d[4],
                                        uint32_t a0, uint32_t a1, uint32_t a2, uint32_t a3,
                                        uint32_t b0, uint32_t b1) {
  asm volatile("mma.sync.aligned.m16n8k16.row.col.f32.f16.f16.f32 "
               "{%0,%1,%2,%3}, {%4,%5,%6,%7}, {%8,%9}, {%0,%1,%2,%3};"
               : "+f"(d[0]), "+f"(d[1]), "+f"(d[2]), "+f"(d[3])
               : "r"(a0), "r"(a1), "r"(a2), "r"(a3), "r"(b0), "r"(b1));
}
__device__ __forceinline__ uint32_t h2bits(__half2 h) { return *(uint32_t*)&h; }

// ---------------------------------------------------------------------------
// prep: w_eff (src+dst), W fragment permute (fp16), COUNT zeroing — one launch
// ---------------------------------------------------------------------------
__global__ void k_prep(const float* __restrict__ W_src, const float* __restrict__ W_dst,
                       const float* __restrict__ a_w) {
  int gid = blockIdx.x * blockDim.x + threadIdx.x;
  int stride = gridDim.x * blockDim.x;

  for (int j = gid; j < N_NODES; j += stride) COUNT[j] = 0;

  for (int t = gid; t < H_HEADS * IN_DIM; t += stride) {
    int h = t / IN_DIM, d = t % IN_DIM;
    float as_acc = 0.f, ad_acc = 0.f;
    #pragma unroll 8
    for (int o = 0; o < OUT_DIM; o++) {
      as_acc += a_w[h * 2 * OUT_DIM + o]           * W_src[(h * OUT_DIM + o) * IN_DIM + d];
      ad_acc += a_w[h * 2 * OUT_DIM + OUT_DIM + o] * W_dst[(h * OUT_DIM + o) * IN_DIM + d];
    }
    W_EFF_SRC[t] = as_acc;
    W_EFF_DST[t] = ad_acc;
  }

  for (int o = gid; o < HO * IN_DIM / 4; o += stride) {
    int lane = o & 31, kk = (o >> 5) & 7, tile = o >> 8;
    int g = lane >> 2, q = lane & 3;
    int n = tile * 8 + g;
    int k0 = kk * 16 + 2 * q;
    const float* wr = &W_src[n * IN_DIM];
    __half2 b0 = __floats2half2_rn(wr[k0],     wr[k0 + 1]);
    __half2 b1 = __floats2half2_rn(wr[k0 + 8], wr[k0 + 9]);
    W_FRH[o] = make_uint2(h2bits(b0), h2bits(b1));
  }
}

// ---------------------------------------------------------------------------
// main fused kernel: blocks [0,ZBLK) = z_src GEMM (+fused fp32 s_src);
// blocks [ZBLK,..) = s_dst stream (warp per node), overlaps GEMM tail.
// ---------------------------------------------------------------------------
#define SMX_BYTES (BLK_M * PADH * 2)          // 34816
#define SM_TOT    (SMX_BYTES + 32768)         // 67584

__global__ void __launch_bounds__(512, 2) k_main(const float* __restrict__ h_src,
                                                 const float* __restrict__ h_dst) {
  const int tid  = threadIdx.x;
  const int wid  = tid >> 5;
  const int lane = tid & 31;

  if (blockIdx.x >= ZBLK) {
    int node = (blockIdx.x - ZBLK) * 16 + wid;
    if (node >= N_NODES) return;
    float4 x = ((const float4*)(h_dst + (size_t)node * IN_DIM))[lane];
    float4 a = ((const float4*)W_EFF_DST)[lane];
    float4 b = ((const float4*)(W_EFF_DST + IN_DIM))[lane];
    float s0 = x.x*a.x + x.y*a.y + x.z*a.z + x.w*a.w;
    float s1 = x.x*b.x + x.y*b.y + x.z*b.z + x.w*b.w;
    #pragma unroll
    for (int m = 16; m; m >>= 1) {
      s0 += __shfl_xor_sync(0xffffffffu, s0, m);
      s1 += __shfl_xor_sync(0xffffffffu, s1, m);
    }
    if (lane == 0) { S_DST[node * 2] = s0; S_DST[node * 2 + 1] = s1; }
    return;
  }

  extern __shared__ char sm[];
  __half* Xs  = (__half*)sm;                  // [BLK_M][PADH] fp16
  uint2*  Bfr = (uint2*)(sm + SMX_BYTES);
  const int nbase = blockIdx.x * BLK_M;

  float4 ws0 = ((const float4*)W_EFF_SRC)[lane];
  float4 ws1 = ((const float4*)(W_EFF_SRC + IN_DIM))[lane];

  #pragma unroll
  for (int it = 0; it < (BLK_M * 32) / 512; it++) {
    int row = wid + it * 16;
    int gn = nbase + row;
    float4 v = make_float4(0.f, 0.f, 0.f, 0.f);
    if (gn < N_NODES) v = *(const float4*)&h_src[(size_t)gn * IN_DIM + lane * 4];
    float p0 = v.x*ws0.x + v.y*ws0.y + v.z*ws0.z + v.w*ws0.w;
    float p1 = v.x*ws1.x + v.y*ws1.y + v.z*ws1.z + v.w*ws1.w;
    #pragma unroll
    for (int m = 16; m; m >>= 1) {
      p0 += __shfl_xor_sync(0xffffffffu, p0, m);
      p1 += __shfl_xor_sync(0xffffffffu, p1, m);
    }
    if (lane == 0 && gn < N_NODES) { S_SRC[gn * 2] = p0; S_SRC[gn * 2 + 1] = p1; }
    __half2 h01 = __floats2half2_rn(v.x, v.y);
    __half2 h23 = __floats2half2_rn(v.z, v.w);
    *(uint2*)&Xs[row * PADH + lane * 4] = make_uint2(h2bits(h01), h2bits(h23));
  }
  {
    const uint4* src = (const uint4*)W_FRH;
    uint4* dst = (uint4*)Bfr;
    #pragma unroll
    for (int it = 0; it < 2048 / 512; it++)
      dst[tid + it * 512] = src[tid + it * 512];
  }
  __syncthreads();

  const int wm = wid >> 1;
  const int wn = wid & 1;
  const int g  = lane >> 2;
  const int q  = lane & 3;

  float d[8][4];
  #pragma unroll
  for (int j = 0; j < 8; j++)
    #pragma unroll
    for (int c = 0; c < 4; c++) d[j][c] = 0.f;

  const __half* Ar0 = &Xs[(wm * 16 + g) * PADH];
  const __half* Ar1 = Ar0 + 8 * PADH;

  #pragma unroll
  for (int kk = 0; kk < 8; kk++) {
    int c = kk * 16 + 2 * q;
    uint32_t a0 = *(const uint32_t*)&Ar0[c];
    uint32_t a1 = *(const uint32_t*)&Ar1[c];
    uint32_t a2 = *(const uint32_t*)&Ar0[c + 8];
    uint32_t a3 = *(const uint32_t*)&Ar1[c + 8];
    #pragma unroll
    for (int j = 0; j < 8; j++) {
      uint2 b = Bfr[((wn * 8 + j) * 8 + kk) * 32 + lane];
      mma_f16(d[j], a0, a1, a2, a3, b.x, b.y);
    }
  }

  int r0 = nbase + wm * 16 + g;
  int r1 = r0 + 8;
  bool v0 = (r0 < N_NODES), v1 = (r1 < N_NODES);
  #pragma unroll
  for (int j = 0; j < 8; j++) {
    int col = (wn * 8 + j) * 8 + q * 2;
    if (v0) *(__half2*)&Z_H[(size_t)r0 * HO + col] = __floats2half2_rn(d[j][0], d[j][1]);
    if (v1) *(__half2*)&Z_H[(size_t)r1 * HO + col] = __floats2half2_rn(d[j][2], d[j][3]);
  }
}

// ---------------------------------------------------------------------------
// edge pass: ex = __expf(leaky_relu(s_src+s_dst)) (max-free, |e|<~8; __expf's
// ~1e-6 rel err absorbed by half rounding of ex).
// ---------------------------------------------------------------------------
__global__ void k_edge1(const int* __restrict__ src_idx, const int* __restrict__ dst_idx) {
  int e = blockIdx.x * blockDim.x + threadIdx.x;
  if (e >= E_EDGES) return;
  int s = src_idx[e], d = dst_idx[e];
  float2 ss = *(const float2*)&S_SRC[s * 2];
  float2 sd = *(const float2*)&S_DST[d * 2];
  float e0 = ss.x + sd.x; e0 = e0 > 0.f ? e0 : 0.01f * e0;
  float e1 = ss.y + sd.y; e1 = e1 > 0.f ? e1 : 0.01f * e1;
  float x0 = __expf(e0), x1 = __expf(e1);
  int c = atomicAdd(&COUNT[d], 1);
  if (c < CAP)
    ENT[(size_t)d * CAP + c] = make_uint2(h2bits(__floats2half2_rn(x0, x1)), (uint32_t)s);
}

// ---------------------------------------------------------------------------
// gather pass: warp per dst node, FULL warp per edge, lane owns 4 columns.
// Per edge (warp-wide): 1 uniform LDG.64 (ENT, exact trip count), 1 LDG.64 z
// (8B/lane x 32 lanes = 256B row), 4 cvt + 4 FFMA + 2 FADD. No shuffles in
// the loop, no trip-count waste. Denominators redundantly accumulated in all
// lanes; normalize locally; one shfl-16 head combine; 16-lane 256B store.
// ---------------------------------------------------------------------------
__global__ void __launch_bounds__(256) k_edge2d(float* __restrict__ out) {
  int node = (blockIdx.x * blockDim.x + threadIdx.x) >> 5;
  int lane = threadIdx.x & 31;
  if (node >= N_NODES) return;

  int deg = COUNT[node];
  deg = deg < CAP ? deg : CAP;

  const uint2* entp = &ENT[(size_t)node * CAP];
  const __half* zcol = Z_H + lane * 4;       // cols lane*4 .. lane*4+3
  const bool head0 = (lane < 16);

  float dn0 = 0.f, dn1 = 0.f;
  float a0 = 0.f, a1 = 0.f, a2 = 0.f, a3 = 0.f;

  #pragma unroll 4
  for (int c = 0; c < deg; c++) {
    uint2 ent = entp[c];                     // uniform across warp: 1 wavefront
    float2 ex = __half22float2(*(__half2*)&ent.x);
    dn0 += ex.x; dn1 += ex.y;
    float al = head0 ? ex.x : ex.y;
    uint2 raw = *(const uint2*)(zcol + ((size_t)ent.y << 7));  // ent.y * HO halves
    float2 z01 = __half22float2(*(__half2*)&raw.x);
    float2 z23 = __half22float2(*(__half2*)&raw.y);
    a0 = fmaf(al, z01.x, a0);
    a1 = fmaf(al, z01.y, a1);
    a2 = fmaf(al, z23.x, a2);
    a3 = fmaf(al, z23.y, a3);
  }

  // normalize per head (deg==0 -> inv=0 -> exact zeros); lane-local since all
  // lanes hold identical denominators.
  float inv0 = dn0 > 0.f ? 1.f / dn0 : 0.f;
  float inv1 = dn1 > 0.f ? 1.f / dn1 : 0.f;
  float inv = head0 ? inv0 : inv1;
  a0 *= inv; a1 *= inv; a2 *= inv; a3 *= inv;

  // head combine: lane L (<16, col o=L*4) += lane L+16 (col 64+o)
  a0 += __shfl_xor_sync(0xffffffffu, a0, 16);
  a1 += __shfl_xor_sync(0xffffffffu, a1, 16);
  a2 += __shfl_xor_sync(0xffffffffu, a2, 16);
  a3 += __shfl_xor_sync(0xffffffffu, a3, 16);

  if (lane < 16)
    *(float4*)&out[(size_t)node * OUT_DIM + lane * 4] = make_float4(a0, a1, a2, a3);
}

// ---------------------------------------------------------------------------
extern "C" void kernel_launch(void* const* d_in, const int* in_sizes, int n_in,
                              void* d_out, int out_size) {
  const float* h_src  = (const float*)d_in[0];
  const float* h_dst  = (const float*)d_in[1];
  const float* W_src  = (const float*)d_in[2];
  const float* W_dst  = (const float*)d_in[3];
  const float* a_w    = (const float*)d_in[4];
  const int*   src_ix = (const int*)d_in[5];
  const int*   dst_ix = (const int*)d_in[6];
  float* out = (float*)d_out;

  cudaFuncSetAttribute(k_main, cudaFuncAttributeMaxDynamicSharedMemorySize, SM_TOT);

  k_prep<<<256, 256>>>(W_src, W_dst, a_w);
  k_main<<<ZBLK + SDBLK, 512, SM_TOT>>>(h_src, h_dst);
  k_edge1<<<(E_EDGES + 255) / 256, 256>>>(src_ix, dst_ix);
  // warp per node -> 8 nodes per 256-thread block
  k_edge2d<<<(N_NODES + 7) / 8, 256>>>(out);
}

// round 12
// speedup vs baseline: 1.2009x; 1.2009x over previous
#include <cuda_runtime.h>
#include <cuda_fp16.h>
#include <math.h>
#include <stdint.h>

#define N_NODES 100000
#define E_EDGES 1000000
#define IN_DIM  128
#define OUT_DIM 64
#define H_HEADS 2
#define HO      (H_HEADS * OUT_DIM)   // 128

#define BLK_M   128
#define ZBLK    ((N_NODES + BLK_M - 1) / BLK_M)   // 782
#define SDBLK   (N_NODES / 16)                    // 6250
#define CAP     64     // max degree slots per dst (Poisson(10): P(deg>=64) ~ 1e-40)
#define PADH    136    // X tile row pad (halves)

// ---- scratch (device globals: allocation-free rule) ----
__device__ __half  Z_H[(size_t)N_NODES * HO];       // z_src fp16, 25.6 MB (L2-resident)
__device__ float   S_SRC[N_NODES * H_HEADS];
__device__ float   S_DST[N_NODES * H_HEADS];
__device__ float   W_EFF_DST[H_HEADS * IN_DIM];
__device__ uint2   W_FRH[HO * IN_DIM / 4];          // W_src fp16, frag-major
__device__ uint2   ENT[(size_t)N_NODES * CAP];      // (half2(ex0,ex1), src) 51.2 MB
__device__ int     COUNT[N_NODES];

// fp16 m16n8k16 MMA, fp32 accumulate (sm_80+ PTX -> Blackwell tensor pipe)
__device__ __forceinline__ void mma_f16(float d[4],
                                        uint32_t a0, uint32_t a1, uint32_t a2, uint32_t a3,
                                        uint32_t b0, uint32_t b1) {
  asm volatile("mma.sync.aligned.m16n8k16.row.col.f32.f16.f16.f32 "
               "{%0,%1,%2,%3}, {%4,%5,%6,%7}, {%8,%9}, {%0,%1,%2,%3};"
               : "+f"(d[0]), "+f"(d[1]), "+f"(d[2]), "+f"(d[3])
               : "r"(a0), "r"(a1), "r"(a2), "r"(a3), "r"(b0), "r"(b1));
}
__device__ __forceinline__ uint32_t h2bits(__half2 h) { return *(uint32_t*)&h; }

// ---------------------------------------------------------------------------
// prep: w_eff_dst, W fragment permute (fp16), COUNT zeroing — one launch
// ---------------------------------------------------------------------------
__global__ void k_prep(const float* __restrict__ W_src, const float* __restrict__ W_dst,
                       const float* __restrict__ a_w) {
  int gid = blockIdx.x * blockDim.x + threadIdx.x;
  int stride = gridDim.x * blockDim.x;

  for (int j = gid; j < N_NODES; j += stride) COUNT[j] = 0;

  for (int t = gid; t < H_HEADS * IN_DIM; t += stride) {
    int h = t / IN_DIM, d = t % IN_DIM;
    float ad_acc = 0.f;
    #pragma unroll 8
    for (int o = 0; o < OUT_DIM; o++)
      ad_acc += a_w[h * 2 * OUT_DIM + OUT_DIM + o] * W_dst[(h * OUT_DIM + o) * IN_DIM + d];
    W_EFF_DST[t] = ad_acc;
  }

  for (int o = gid; o < HO * IN_DIM / 4; o += stride) {
    int lane = o & 31, kk = (o >> 5) & 7, tile = o >> 8;
    int g = lane >> 2, q = lane & 3;
    int n = tile * 8 + g;
    int k0 = kk * 16 + 2 * q;
    const float* wr = &W_src[n * IN_DIM];
    __half2 b0 = __floats2half2_rn(wr[k0],     wr[k0 + 1]);
    __half2 b1 = __floats2half2_rn(wr[k0 + 8], wr[k0 + 9]);
    W_FRH[o] = make_uint2(h2bits(b0), h2bits(b1));
  }
}

// ---------------------------------------------------------------------------
// main fused kernel: blocks [0,ZBLK) = z_src GEMM, with s_src computed in the
// MMA EPILOGUE (warp wn owns exactly head wn's 64 columns -> warp-local
// reduction, no staging shfl chains). Blocks [ZBLK,..) = s_dst stream.
// ---------------------------------------------------------------------------
#define SMX_BYTES (BLK_M * PADH * 2)          // 34816
#define SM_AS     (SMX_BYTES + 32768)         // a_s: 128 floats
#define SM_TOT    (SM_AS + 512)               // 68096

__global__ void __launch_bounds__(512, 2) k_main(const float* __restrict__ h_src,
                                                 const float* __restrict__ h_dst,
                                                 const float* __restrict__ a_w) {
  const int tid  = threadIdx.x;
  const int wid  = tid >> 5;
  const int lane = tid & 31;

  if (blockIdx.x >= ZBLK) {
    // ---- s_dst path: warp per node, fp32-exact ----
    int node = (blockIdx.x - ZBLK) * 16 + wid;
    if (node >= N_NODES) return;
    float4 x = ((const float4*)(h_dst + (size_t)node * IN_DIM))[lane];
    float4 a = ((const float4*)W_EFF_DST)[lane];
    float4 b = ((const float4*)(W_EFF_DST + IN_DIM))[lane];
    float s0 = x.x*a.x + x.y*a.y + x.z*a.z + x.w*a.w;
    float s1 = x.x*b.x + x.y*b.y + x.z*b.z + x.w*b.w;
    #pragma unroll
    for (int m = 16; m; m >>= 1) {
      s0 += __shfl_xor_sync(0xffffffffu, s0, m);
      s1 += __shfl_xor_sync(0xffffffffu, s1, m);
    }
    if (lane == 0) { S_DST[node * 2] = s0; S_DST[node * 2 + 1] = s1; }
    return;
  }

  extern __shared__ char sm[];
  __half* Xs    = (__half*)sm;                // [BLK_M][PADH] fp16
  uint2*  Bfr   = (uint2*)(sm + SMX_BYTES);
  float*  as_sm = (float*)(sm + SM_AS);       // a_s[col] for col in [0,128)
  const int nbase = blockIdx.x * BLK_M;

  if (tid < HO) as_sm[tid] = a_w[(tid >> 6) * 2 * OUT_DIM + (tid & 63)];

  // stage X (fp16): pure LDG -> cvt -> STS stream, no reductions
  #pragma unroll
  for (int it = 0; it < (BLK_M * 32) / 512; it++) {
    int row = wid + it * 16;
    int gn = nbase + row;
    float4 v = make_float4(0.f, 0.f, 0.f, 0.f);
    if (gn < N_NODES) v = *(const float4*)&h_src[(size_t)gn * IN_DIM + lane * 4];
    __half2 h01 = __floats2half2_rn(v.x, v.y);
    __half2 h23 = __floats2half2_rn(v.z, v.w);
    *(uint2*)&Xs[row * PADH + lane * 4] = make_uint2(h2bits(h01), h2bits(h23));
  }
  // stage W fragments (32KB contiguous copy)
  {
    const uint4* src = (const uint4*)W_FRH;
    uint4* dst = (uint4*)Bfr;
    #pragma unroll
    for (int it = 0; it < 2048 / 512; it++)
      dst[tid + it * 512] = src[tid + it * 512];
  }
  __syncthreads();

  const int wm = wid >> 1;          // m-tile: nodes wm*16 .. +15
  const int wn = wid & 1;           // n-half == head: cols wn*64 .. +63
  const int g  = lane >> 2;
  const int q  = lane & 3;

  float d[8][4];
  #pragma unroll
  for (int j = 0; j < 8; j++)
    #pragma unroll
    for (int c = 0; c < 4; c++) d[j][c] = 0.f;

  const __half* Ar0 = &Xs[(wm * 16 + g) * PADH];
  const __half* Ar1 = Ar0 + 8 * PADH;

  #pragma unroll
  for (int kk = 0; kk < 8; kk++) {
    int c = kk * 16 + 2 * q;
    uint32_t a0 = *(const uint32_t*)&Ar0[c];
    uint32_t a1 = *(const uint32_t*)&Ar1[c];
    uint32_t a2 = *(const uint32_t*)&Ar0[c + 8];
    uint32_t a3 = *(const uint32_t*)&Ar1[c + 8];
    #pragma unroll
    for (int j = 0; j < 8; j++) {
      uint2 b = Bfr[((wn * 8 + j) * 8 + kk) * 32 + lane];
      mma_f16(d[j], a0, a1, a2, a3, b.x, b.y);
    }
  }

  // epilogue: store Z (fp16) + s_src for head wn from fp32 accumulators
  int r0 = nbase + wm * 16 + g;
  int r1 = r0 + 8;
  bool v0 = (r0 < N_NODES), v1 = (r1 < N_NODES);
  float ps0 = 0.f, ps1 = 0.f;
  #pragma unroll
  for (int j = 0; j < 8; j++) {
    int col = (wn * 8 + j) * 8 + q * 2;
    float w0 = as_sm[col], w1 = as_sm[col + 1];
    ps0 += w0 * d[j][0] + w1 * d[j][1];
    ps1 += w0 * d[j][2] + w1 * d[j][3];
    if (v0) *(__half2*)&Z_H[(size_t)r0 * HO + col] = __floats2half2_rn(d[j][0], d[j][1]);
    if (v1) *(__half2*)&Z_H[(size_t)r1 * HO + col] = __floats2half2_rn(d[j][2], d[j][3]);
  }
  // reduce over the 4 q-lanes of row group g
  ps0 += __shfl_xor_sync(0xffffffffu, ps0, 1);
  ps0 += __shfl_xor_sync(0xffffffffu, ps0, 2);
  ps1 += __shfl_xor_sync(0xffffffffu, ps1, 1);
  ps1 += __shfl_xor_sync(0xffffffffu, ps1, 2);
  if (q == 0) {
    if (v0) S_SRC[r0 * 2 + wn] = ps0;
    if (v1) S_SRC[r1 * 2 + wn] = ps1;
  }
}

// ---------------------------------------------------------------------------
// edge pass: ex = __expf(leaky_relu(s_src+s_dst)) (max-free, |e|<~8; __expf's
// ~1e-6 rel err absorbed by half rounding of ex).
// ---------------------------------------------------------------------------
__global__ void k_edge1(const int* __restrict__ src_idx, const int* __restrict__ dst_idx) {
  int e = blockIdx.x * blockDim.x + threadIdx.x;
  if (e >= E_EDGES) return;
  int s = src_idx[e], d = dst_idx[e];
  float2 ss = *(const float2*)&S_SRC[s * 2];
  float2 sd = *(const float2*)&S_DST[d * 2];
  float e0 = ss.x + sd.x; e0 = e0 > 0.f ? e0 : 0.01f * e0;
  float e1 = ss.y + sd.y; e1 = e1 > 0.f ? e1 : 0.01f * e1;
  float x0 = __expf(e0), x1 = __expf(e1);
  int c = atomicAdd(&COUNT[d], 1);
  if (c < CAP)
    ENT[(size_t)d * CAP + c] = make_uint2(h2bits(__floats2half2_rn(x0, x1)), (uint32_t)s);
}

// ---------------------------------------------------------------------------
// gather pass (R10 structure — best measured): TWO INDEPENDENT nodes per warp
// (one per 16-lane half). Per edge: one predicated uniform LDG.64 (ENT), one
// LDG.128 (16B of the z row per lane), 8 cvt + 8 FFMA, 2 FADD. No shuffles in
// the hot loop. 32-bit address math (Z_H spans 25.6MB).
// ---------------------------------------------------------------------------
__global__ void __launch_bounds__(256) k_edge2c(float* __restrict__ out) {
  int gwarp = (blockIdx.x * blockDim.x + threadIdx.x) >> 5;
  int lane  = threadIdx.x & 31;
  const int half = lane >> 4;
  const int hl   = lane & 15;            // column chunk: cols hl*8 .. hl*8+7
  int node = gwarp * 2 + half;
  const bool nodeValid = node < N_NODES;
  const int nd = nodeValid ? node : 0;

  int deg = nodeValid ? COUNT[nd] : 0;
  deg = deg < CAP ? deg : CAP;
  int odeg = __shfl_xor_sync(0xffffffffu, deg, 16);
  int mx = deg > odeg ? deg : odeg;      // shared trip count (predicated lanes idle)

  const uint2* entp = &ENT[(size_t)nd * CAP];
  const char* zb = (const char*)Z_H + (uint32_t)(hl * 16);
  const bool head0 = (hl < 8);

  float dn0 = 0.f, dn1 = 0.f;
  float a0 = 0.f, a1 = 0.f, a2 = 0.f, a3 = 0.f;
  float a4 = 0.f, a5 = 0.f, a6 = 0.f, a7 = 0.f;

  #pragma unroll 4
  for (int c = 0; c < mx; c++) {
    uint2 ent = make_uint2(0u, 0u);
    if (c < deg) ent = entp[c];          // uniform within half-warp
    float2 ex = __half22float2(*(__half2*)&ent.x);
    dn0 += ex.x; dn1 += ex.y;
    float al = head0 ? ex.x : ex.y;
    uint4 raw = *(const uint4*)(zb + (ent.y << 8));   // ent.y * 256B, 32-bit
    float2 z0 = __half22float2(*(__half2*)&raw.x);
    float2 z1 = __half22float2(*(__half2*)&raw.y);
    float2 z2 = __half22float2(*(__half2*)&raw.z);
    float2 z3 = __half22float2(*(__half2*)&raw.w);
    a0 = fmaf(al, z0.x, a0); a1 = fmaf(al, z0.y, a1);
    a2 = fmaf(al, z1.x, a2); a3 = fmaf(al, z1.y, a3);
    a4 = fmaf(al, z2.x, a4); a5 = fmaf(al, z2.y, a5);
    a6 = fmaf(al, z3.x, a6); a7 = fmaf(al, z3.y, a7);
  }

  // normalize per head (deg==0 -> inv=0 -> exact zeros); lane-local
  float inv0 = dn0 > 0.f ? 1.f / dn0 : 0.f;
  float inv1 = dn1 > 0.f ? 1.f / dn1 : 0.f;
  float inv = head0 ? inv0 : inv1;
  a0 *= inv; a1 *= inv; a2 *= inv; a3 *= inv;
  a4 *= inv; a5 *= inv; a6 *= inv; a7 *= inv;

  // head combine within the half: lane hl (<8) += lane hl+8 (cols 64+o)
  a0 += __shfl_xor_sync(0xffffffffu, a0, 8);
  a1 += __shfl_xor_sync(0xffffffffu, a1, 8);
  a2 += __shfl_xor_sync(0xffffffffu, a2, 8);
  a3 += __shfl_xor_sync(0xffffffffu, a3, 8);
  a4 += __shfl_xor_sync(0xffffffffu, a4, 8);
  a5 += __shfl_xor_sync(0xffffffffu, a5, 8);
  a6 += __shfl_xor_sync(0xffffffffu, a6, 8);
  a7 += __shfl_xor_sync(0xffffffffu, a7, 8);

  if (hl < 8 && nodeValid) {
    float* p = out + (size_t)node * OUT_DIM + hl * 8;
    *(float4*)p       = make_float4(a0, a1, a2, a3);
    *(float4*)(p + 4) = make_float4(a4, a5, a6, a7);
  }
}

// ---------------------------------------------------------------------------
extern "C" void kernel_launch(void* const* d_in, const int* in_sizes, int n_in,
                              void* d_out, int out_size) {
  const float* h_src  = (const float*)d_in[0];
  const float* h_dst  = (const float*)d_in[1];
  const float* W_src  = (const float*)d_in[2];
  const float* W_dst  = (const float*)d_in[3];
  const float* a_w    = (const float*)d_in[4];
  const int*   src_ix = (const int*)d_in[5];
  const int*   dst_ix = (const int*)d_in[6];
  float* out = (float*)d_out;

  cudaFuncSetAttribute(k_main, cudaFuncAttributeMaxDynamicSharedMemorySize, SM_TOT);

  k_prep<<<256, 256>>>(W_src, W_dst, a_w);
  k_main<<<ZBLK + SDBLK, 512, SM_TOT>>>(h_src, h_dst, a_w);
  k_edge1<<<(E_EDGES + 255) / 256, 256>>>(src_ix, dst_ix);
  // 2 nodes per warp -> 16 nodes per 256-thread block
  k_edge2c<<<(N_NODES + 15) / 16, 256>>>(out);
}

// round 13
// speedup vs baseline: 1.3185x; 1.0979x over previous
#include <cuda_runtime.h>
#include <cuda_fp16.h>
#include <math.h>
#include <stdint.h>

#define N_NODES 100000
#define E_EDGES 1000000
#define IN_DIM  128
#define OUT_DIM 64
#define H_HEADS 2
#define HO      (H_HEADS * OUT_DIM)   // 128

#define BLK_M   128
#define ZBLK    ((N_NODES + BLK_M - 1) / BLK_M)   // 782
#define SDBLK   ((N_NODES + 63) / 64)             // 1563 (64 nodes per block)
#define CAP     64     // max degree slots per dst (Poisson(10): P(deg>=64) ~ 1e-40)
#define PADH    136    // X tile row pad (halves)

// ---- scratch (device globals: allocation-free rule) ----
__device__ __half  Z_H[(size_t)N_NODES * HO];       // z_src fp16, 25.6 MB (L2-resident)
__device__ float   S_SRC[N_NODES * H_HEADS];
__device__ float   S_DST[N_NODES * H_HEADS];
__device__ float   W_EFF_DST[H_HEADS * IN_DIM];
__device__ uint2   W_FRH[HO * IN_DIM / 4];          // W_src fp16, frag-major
__device__ uint2   ENT[(size_t)N_NODES * CAP];      // (half2(ex0,ex1), src*256) 51.2 MB
__device__ int     COUNT[N_NODES];

// fp16 m16n8k16 MMA, fp32 accumulate (sm_80+ PTX -> Blackwell tensor pipe)
__device__ __forceinline__ void mma_f16(float d[4],
                                        uint32_t a0, uint32_t a1, uint32_t a2, uint32_t a3,
                                        uint32_t b0, uint32_t b1) {
  asm volatile("mma.sync.aligned.m16n8k16.row.col.f32.f16.f16.f32 "
               "{%0,%1,%2,%3}, {%4,%5,%6,%7}, {%8,%9}, {%0,%1,%2,%3};"
               : "+f"(d[0]), "+f"(d[1]), "+f"(d[2]), "+f"(d[3])
               : "r"(a0), "r"(a1), "r"(a2), "r"(a3), "r"(b0), "r"(b1));
}
__device__ __forceinline__ uint32_t h2bits(__half2 h) { return *(uint32_t*)&h; }

// ---------------------------------------------------------------------------
// prep: w_eff_dst, W fragment permute (fp16), COUNT zeroing — one launch
// ---------------------------------------------------------------------------
__global__ void k_prep(const float* __restrict__ W_src, const float* __restrict__ W_dst,
                       const float* __restrict__ a_w) {
  int gid = blockIdx.x * blockDim.x + threadIdx.x;
  int stride = gridDim.x * blockDim.x;

  for (int j = gid; j < N_NODES; j += stride) COUNT[j] = 0;

  for (int t = gid; t < H_HEADS * IN_DIM; t += stride) {
    int h = t / IN_DIM, d = t % IN_DIM;
    float ad_acc = 0.f;
    #pragma unroll 8
    for (int o = 0; o < OUT_DIM; o++)
      ad_acc += a_w[h * 2 * OUT_DIM + OUT_DIM + o] * W_dst[(h * OUT_DIM + o) * IN_DIM + d];
    W_EFF_DST[t] = ad_acc;
  }

  for (int o = gid; o < HO * IN_DIM / 4; o += stride) {
    int lane = o & 31, kk = (o >> 5) & 7, tile = o >> 8;
    int g = lane >> 2, q = lane & 3;
    int n = tile * 8 + g;
    int k0 = kk * 16 + 2 * q;
    const float* wr = &W_src[n * IN_DIM];
    __half2 b0 = __floats2half2_rn(wr[k0],     wr[k0 + 1]);
    __half2 b1 = __floats2half2_rn(wr[k0 + 8], wr[k0 + 9]);
    W_FRH[o] = make_uint2(h2bits(b0), h2bits(b1));
  }
}

// ---------------------------------------------------------------------------
// main fused kernel: blocks [0,ZBLK) = z_src GEMM with s_src in the MMA
// epilogue; blocks [ZBLK,..) = s_dst stream (4 nodes per warp, 4 upfront
// independent loads for MLP).
// ---------------------------------------------------------------------------
#define SMX_BYTES (BLK_M * PADH * 2)          // 34816
#define SM_AS     (SMX_BYTES + 32768)         // a_s: 128 floats
#define SM_TOT    (SM_AS + 512)               // 68096

__global__ void __launch_bounds__(512, 2) k_main(const float* __restrict__ h_src,
                                                 const float* __restrict__ h_dst,
                                                 const float* __restrict__ a_w) {
  const int tid  = threadIdx.x;
  const int wid  = tid >> 5;
  const int lane = tid & 31;

  if (blockIdx.x >= ZBLK) {
    // ---- s_dst path: 4 nodes per warp, fp32-exact ----
    int nb = (blockIdx.x - ZBLK) * 64 + wid * 4;
    float4 a = ((const float4*)W_EFF_DST)[lane];
    float4 b = ((const float4*)(W_EFF_DST + IN_DIM))[lane];
    float4 x[4];
    #pragma unroll
    for (int i = 0; i < 4; i++) {
      int n = nb + i;
      x[i] = (n < N_NODES) ? ((const float4*)(h_dst + (size_t)n * IN_DIM))[lane]
                           : make_float4(0.f, 0.f, 0.f, 0.f);
    }
    float s0[4], s1[4];
    #pragma unroll
    for (int i = 0; i < 4; i++) {
      s0[i] = x[i].x*a.x + x[i].y*a.y + x[i].z*a.z + x[i].w*a.w;
      s1[i] = x[i].x*b.x + x[i].y*b.y + x[i].z*b.z + x[i].w*b.w;
    }
    #pragma unroll
    for (int m = 16; m; m >>= 1) {
      #pragma unroll
      for (int i = 0; i < 4; i++) {
        s0[i] += __shfl_xor_sync(0xffffffffu, s0[i], m);
        s1[i] += __shfl_xor_sync(0xffffffffu, s1[i], m);
      }
    }
    if (lane == 0) {
      #pragma unroll
      for (int i = 0; i < 4; i++) {
        int n = nb + i;
        if (n < N_NODES) { S_DST[n * 2] = s0[i]; S_DST[n * 2 + 1] = s1[i]; }
      }
    }
    return;
  }

  extern __shared__ char sm[];
  __half* Xs    = (__half*)sm;                // [BLK_M][PADH] fp16
  uint2*  Bfr   = (uint2*)(sm + SMX_BYTES);
  float*  as_sm = (float*)(sm + SM_AS);       // a_s[col] for col in [0,128)
  const int nbase = blockIdx.x * BLK_M;

  if (tid < HO) as_sm[tid] = a_w[(tid >> 6) * 2 * OUT_DIM + (tid & 63)];

  // stage X (fp16): pure LDG -> cvt -> STS stream
  #pragma unroll
  for (int it = 0; it < (BLK_M * 32) / 512; it++) {
    int row = wid + it * 16;
    int gn = nbase + row;
    float4 v = make_float4(0.f, 0.f, 0.f, 0.f);
    if (gn < N_NODES) v = *(const float4*)&h_src[(size_t)gn * IN_DIM + lane * 4];
    __half2 h01 = __floats2half2_rn(v.x, v.y);
    __half2 h23 = __floats2half2_rn(v.z, v.w);
    *(uint2*)&Xs[row * PADH + lane * 4] = make_uint2(h2bits(h01), h2bits(h23));
  }
  // stage W fragments (32KB contiguous copy)
  {
    const uint4* src = (const uint4*)W_FRH;
    uint4* dst = (uint4*)Bfr;
    #pragma unroll
    for (int it = 0; it < 2048 / 512; it++)
      dst[tid + it * 512] = src[tid + it * 512];
  }
  __syncthreads();

  const int wm = wid >> 1;          // m-tile: nodes wm*16 .. +15
  const int wn = wid & 1;           // n-half == head: cols wn*64 .. +63
  const int g  = lane >> 2;
  const int q  = lane & 3;

  float d[8][4];
  #pragma unroll
  for (int j = 0; j < 8; j++)
    #pragma unroll
    for (int c = 0; c < 4; c++) d[j][c] = 0.f;

  const __half* Ar0 = &Xs[(wm * 16 + g) * PADH];
  const __half* Ar1 = Ar0 + 8 * PADH;

  #pragma unroll
  for (int kk = 0; kk < 8; kk++) {
    int c = kk * 16 + 2 * q;
    uint32_t a0 = *(const uint32_t*)&Ar0[c];
    uint32_t a1 = *(const uint32_t*)&Ar1[c];
    uint32_t a2 = *(const uint32_t*)&Ar0[c + 8];
    uint32_t a3 = *(const uint32_t*)&Ar1[c + 8];
    #pragma unroll
    for (int j = 0; j < 8; j++) {
      uint2 b = Bfr[((wn * 8 + j) * 8 + kk) * 32 + lane];
      mma_f16(d[j], a0, a1, a2, a3, b.x, b.y);
    }
  }

  // epilogue: store Z (fp16) + s_src for head wn from fp32 accumulators
  int r0 = nbase + wm * 16 + g;
  int r1 = r0 + 8;
  bool v0 = (r0 < N_NODES), v1 = (r1 < N_NODES);
  float ps0 = 0.f, ps1 = 0.f;
  #pragma unroll
  for (int j = 0; j < 8; j++) {
    int col = (wn * 8 + j) * 8 + q * 2;
    float w0 = as_sm[col], w1 = as_sm[col + 1];
    ps0 += w0 * d[j][0] + w1 * d[j][1];
    ps1 += w0 * d[j][2] + w1 * d[j][3];
    if (v0) *(__half2*)&Z_H[(size_t)r0 * HO + col] = __floats2half2_rn(d[j][0], d[j][1]);
    if (v1) *(__half2*)&Z_H[(size_t)r1 * HO + col] = __floats2half2_rn(d[j][2], d[j][3]);
  }
  ps0 += __shfl_xor_sync(0xffffffffu, ps0, 1);
  ps0 += __shfl_xor_sync(0xffffffffu, ps0, 2);
  ps1 += __shfl_xor_sync(0xffffffffu, ps1, 1);
  ps1 += __shfl_xor_sync(0xffffffffu, ps1, 2);
  if (q == 0) {
    if (v0) S_SRC[r0 * 2 + wn] = ps0;
    if (v1) S_SRC[r1 * 2 + wn] = ps1;
  }
}

// ---------------------------------------------------------------------------
// edge pass: ex = __expf(leaky_relu(s_src+s_dst)); ENT stores the PRE-SHIFTED
// z byte offset (src*256) so the gather kernel does zero address math.
// ---------------------------------------------------------------------------
__global__ void k_edge1(const int* __restrict__ src_idx, const int* __restrict__ dst_idx) {
  int e = blockIdx.x * blockDim.x + threadIdx.x;
  if (e >= E_EDGES) return;
  int s = src_idx[e], d = dst_idx[e];
  float2 ss = *(const float2*)&S_SRC[s * 2];
  float2 sd = *(const float2*)&S_DST[d * 2];
  float e0 = ss.x + sd.x; e0 = e0 > 0.f ? e0 : 0.01f * e0;
  float e1 = ss.y + sd.y; e1 = e1 > 0.f ? e1 : 0.01f * e1;
  float x0 = __expf(e0), x1 = __expf(e1);
  int c = atomicAdd(&COUNT[d], 1);
  if (c < CAP)
    ENT[(size_t)d * CAP + c] =
      make_uint2(h2bits(__floats2half2_rn(x0, x1)), (uint32_t)s << 8);
}

// ---------------------------------------------------------------------------
// gather pass: TWO INDEPENDENT nodes per warp (16-lane halves). Per edge:
// one predicated uniform LDG.64 (ENT), one LDG.128 (16B of z row per lane),
// 8 cvt + 8 FFMA, 2 FADD. launch_bounds(256,8) caps regs at 32 -> 100%
// occupancy cap to hide gather latency.
// ---------------------------------------------------------------------------
__global__ void __launch_bounds__(256, 8) k_edge2c(float* __restrict__ out) {
  int gwarp = (blockIdx.x * blockDim.x + threadIdx.x) >> 5;
  int lane  = threadIdx.x & 31;
  const int half = lane >> 4;
  const int hl   = lane & 15;            // column chunk: cols hl*8 .. hl*8+7
  int node = gwarp * 2 + half;
  const bool nodeValid = node < N_NODES;
  const int nd = nodeValid ? node : 0;

  int deg = nodeValid ? COUNT[nd] : 0;
  deg = deg < CAP ? deg : CAP;
  int odeg = __shfl_xor_sync(0xffffffffu, deg, 16);
  int mx = deg > odeg ? deg : odeg;      // shared trip count

  const uint2* entp = &ENT[(size_t)nd * CAP];
  const char* zb = (const char*)Z_H + (uint32_t)(hl * 16);
  const bool head0 = (hl < 8);

  float dn0 = 0.f, dn1 = 0.f;
  float a0 = 0.f, a1 = 0.f, a2 = 0.f, a3 = 0.f;
  float a4 = 0.f, a5 = 0.f, a6 = 0.f, a7 = 0.f;

  #pragma unroll 2
  for (int c = 0; c < mx; c++) {
    uint2 ent = make_uint2(0u, 0u);
    if (c < deg) ent = entp[c];          // uniform within half-warp
    float2 ex = __half22float2(*(__half2*)&ent.x);
    dn0 += ex.x; dn1 += ex.y;
    float al = head0 ? ex.x : ex.y;
    uint4 raw = *(const uint4*)(zb + ent.y);          // offset pre-shifted
    float2 z0 = __half22float2(*(__half2*)&raw.x);
    float2 z1 = __half22float2(*(__half2*)&raw.y);
    float2 z2 = __half22float2(*(__half2*)&raw.z);
    float2 z3 = __half22float2(*(__half2*)&raw.w);
    a0 = fmaf(al, z0.x, a0); a1 = fmaf(al, z0.y, a1);
    a2 = fmaf(al, z1.x, a2); a3 = fmaf(al, z1.y, a3);
    a4 = fmaf(al, z2.x, a4); a5 = fmaf(al, z2.y, a5);
    a6 = fmaf(al, z3.x, a6); a7 = fmaf(al, z3.y, a7);
  }

  float inv0 = dn0 > 0.f ? 1.f / dn0 : 0.f;
  float inv1 = dn1 > 0.f ? 1.f / dn1 : 0.f;
  float inv = head0 ? inv0 : inv1;
  a0 *= inv; a1 *= inv; a2 *= inv; a3 *= inv;
  a4 *= inv; a5 *= inv; a6 *= inv; a7 *= inv;

  a0 += __shfl_xor_sync(0xffffffffu, a0, 8);
  a1 += __shfl_xor_sync(0xffffffffu, a1, 8);
  a2 += __shfl_xor_sync(0xffffffffu, a2, 8);
  a3 += __shfl_xor_sync(0xffffffffu, a3, 8);
  a4 += __shfl_xor_sync(0xffffffffu, a4, 8);
  a5 += __shfl_xor_sync(0xffffffffu, a5, 8);
  a6 += __shfl_xor_sync(0xffffffffu, a6, 8);
  a7 += __shfl_xor_sync(0xffffffffu, a7, 8);

  if (hl < 8 && nodeValid) {
    float* p = out + (size_t)node * OUT_DIM + hl * 8;
    *(float4*)p       = make_float4(a0, a1, a2, a3);
    *(float4*)(p + 4) = make_float4(a4, a5, a6, a7);
  }
}

// ---------------------------------------------------------------------------
extern "C" void kernel_launch(void* const* d_in, const int* in_sizes, int n_in,
                              void* d_out, int out_size) {
  const float* h_src  = (const float*)d_in[0];
  const float* h_dst  = (const float*)d_in[1];
  const float* W_src  = (const float*)d_in[2];
  const float* W_dst  = (const float*)d_in[3];
  const float* a_w    = (const float*)d_in[4];
  const int*   src_ix = (const int*)d_in[5];
  const int*   dst_ix = (const int*)d_in[6];
  float* out = (float*)d_out;

  cudaFuncSetAttribute(k_main, cudaFuncAttributeMaxDynamicSharedMemorySize, SM_TOT);

  k_prep<<<256, 256>>>(W_src, W_dst, a_w);
  k_main<<<ZBLK + SDBLK, 512, SM_TOT>>>(h_src, h_dst, a_w);
  k_edge1<<<(E_EDGES + 255) / 256, 256>>>(src_ix, dst_ix);
  k_edge2c<<<(N_NODES + 15) / 16, 256>>>(out);
}